// round 13
// baseline (speedup 1.0000x reference)
#include <cuda_runtime.h>
#include <cuda_bf16.h>
#include <cstdint>
#include <math.h>

#define BB 2
#define LL 2048
#define DM 1024
#define DI 2048
#define DS 16
#define DR 64
#define NXD 96          // DR + 2*DS
#define MM (BB*LL)      // 4096

#define NCH   32        // time chunks for parallel scan
#define CHL   64        // chunk length (NCH*CHL == LL)

// CTA tile 128(M) x 64(N), BK=32, 4-stage pipeline.
// Stage: Ah,Al (128x32 bf16 = 8KB ea) + Bh,Bl (64x32 = 4KB ea) = 24KB
#define OFF_AL   8192
#define OFF_BH   16384
#define OFF_BL   20480
#define STAGE_B  24576
#define NSTAGE   4
#define SMEM_B   (NSTAGE * STAGE_B)   // 98304 -> 2 CTAs/SM

// ---------------- fp32 scratch ----------------
__device__ float g_xz[(size_t)MM * (2*DI)];
__device__ float g_xc[(size_t)MM * DI];
__device__ float g_xdbl[(size_t)MM * NXD];
__device__ float g_delta[(size_t)MM * DI];
__device__ float g_part[(size_t)8 * MM * NXD];   // split-K partials for G3a

// parallel-scan chunk state: [b][ch][d][n]
__device__ float gA_P [(size_t)BB * NCH * DI * DS];
__device__ float gA_h [(size_t)BB * NCH * DI * DS];
__device__ float gB_in[(size_t)BB * NCH * DI * DS];

// ---------------- bf16 hi/lo operand buffers ----------------
__device__ __nv_bfloat16 g_x_hi [(size_t)MM * DM],     g_x_lo [(size_t)MM * DM];
__device__ __nv_bfloat16 g_w1_hi[(size_t)2*DI * DM],   g_w1_lo[(size_t)2*DI * DM];
__device__ __nv_bfloat16 g_wx_hi[(size_t)NXD * DI],    g_wx_lo[(size_t)NXD * DI];
__device__ __nv_bfloat16 g_wd_hi[(size_t)DI * DR],     g_wd_lo[(size_t)DI * DR];
__device__ __nv_bfloat16 g_wo_hi[(size_t)DM * DI],     g_wo_lo[(size_t)DM * DI];
__device__ __nv_bfloat16 g_wf_hi[(size_t)DM * DM],     g_wf_lo[(size_t)DM * DM];
__device__ __nv_bfloat16 g_xc_hi[(size_t)MM * DI],     g_xc_lo[(size_t)MM * DI];
__device__ __nv_bfloat16 g_xd_hi[(size_t)MM * NXD],    g_xd_lo[(size_t)MM * NXD];
__device__ __nv_bfloat16 g_y_hi [(size_t)MM * DI],     g_y_lo [(size_t)MM * DI];
__device__ __nv_bfloat16 g_o1_hi[(size_t)MM * DM],     g_o1_lo[(size_t)MM * DM];

// ---------------- helpers ----------------
__device__ __forceinline__ void mma_bf16(float* c, const uint32_t* a, const uint32_t* b) {
    asm volatile(
        "mma.sync.aligned.m16n8k16.row.col.f32.bf16.bf16.f32 "
        "{%0,%1,%2,%3}, {%4,%5,%6,%7}, {%8,%9}, {%0,%1,%2,%3};"
        : "+f"(c[0]), "+f"(c[1]), "+f"(c[2]), "+f"(c[3])
        : "r"(a[0]), "r"(a[1]), "r"(a[2]), "r"(a[3]), "r"(b[0]), "r"(b[1]));
}
__device__ __forceinline__ void ldsm_x4(uint32_t* r, uint32_t addr) {
    asm volatile("ldmatrix.sync.aligned.m8n8.x4.shared.b16 {%0,%1,%2,%3}, [%4];"
        : "=r"(r[0]), "=r"(r[1]), "=r"(r[2]), "=r"(r[3]) : "r"(addr));
}
__device__ __forceinline__ void cp16(uint32_t dst, const void* src, bool valid) {
    int sz = valid ? 16 : 0;
    asm volatile("cp.async.cg.shared.global [%0], [%1], 16, %2;"
        :: "r"(dst), "l"(src), "r"(sz));
}
__device__ __forceinline__ uint32_t pack_hi(float a, float b) {
    __nv_bfloat16 h0 = __float2bfloat16_rn(a), h1 = __float2bfloat16_rn(b);
    return (uint32_t)__bfloat16_as_ushort(h0) | ((uint32_t)__bfloat16_as_ushort(h1) << 16);
}
__device__ __forceinline__ uint32_t pack_lo(float a, float b) {
    __nv_bfloat16 h0 = __float2bfloat16_rn(a), h1 = __float2bfloat16_rn(b);
    float r0 = a - __bfloat162float(h0), r1 = b - __bfloat162float(h1);
    __nv_bfloat16 l0 = __float2bfloat16_rn(r0), l1 = __float2bfloat16_rn(r1);
    return (uint32_t)__bfloat16_as_ushort(l0) | ((uint32_t)__bfloat16_as_ushort(l1) << 16);
}
// swizzled byte offset for 64B-wide tiles packed as row-pairs into 128B lines.
// r = row, c16 = 16B chunk within row (0..3). Conflict-free for ldmatrix.
__device__ __forceinline__ uint32_t sw32(int r, int c16) {
    const int rp  = r >> 1;
    const int idx = (((r & 1) << 2) | c16) ^ (rp & 7);
    return (uint32_t)(rp * 128 + (idx << 4));
}

// ---------------- split fp32 -> bf16 hi/lo ----------------
__global__ __launch_bounds__(256)
void split4_kernel(const float4* __restrict__ src, uint2* __restrict__ hi,
                   uint2* __restrict__ lo, int n4)
{
    int i = blockIdx.x * blockDim.x + threadIdx.x;
    if (i >= n4) return;
    float4 v = src[i];
    hi[i] = make_uint2(pack_hi(v.x, v.y), pack_hi(v.z, v.w));
    lo[i] = make_uint2(pack_lo(v.x, v.y), pack_lo(v.z, v.w));
}

__global__ __launch_bounds__(256)
void split_rest_kernel(const float4* s0, uint2* h0, uint2* l0, int n0,
                       const float4* s1, uint2* h1, uint2* l1, int n1,
                       const float4* s2, uint2* h2, uint2* l2, int n2,
                       const float4* s3, uint2* h3, uint2* l3, int n3)
{
    int i = blockIdx.x * blockDim.x + threadIdx.x;
    const float4* s; uint2 *h, *l; int j;
    if (i < n0)                { s = s0; h = h0; l = l0; j = i; }
    else if (i < n0+n1)        { s = s1; h = h1; l = l1; j = i - n0; }
    else if (i < n0+n1+n2)     { s = s2; h = h2; l = l2; j = i - n0 - n1; }
    else if (i < n0+n1+n2+n3)  { s = s3; h = h3; l = l3; j = i - n0 - n1 - n2; }
    else return;
    float4 v = s[j];
    h[j] = make_uint2(pack_hi(v.x, v.y), pack_hi(v.z, v.w));
    l[j] = make_uint2(pack_lo(v.x, v.y), pack_lo(v.z, v.w));
}

// ================= HMMA GEMM: C[M,N] = A[M,K] * B[N,K]^T =================
// bf16x3 split. CTA 128x64, 256 threads, 8 warps (warptile 32x32), BK=32,
// 4-stage cp.async pipeline with ONE sync per chunk, 2 CTAs/SM.
template<int EPI, bool F32S, bool HLS>
__global__ __launch_bounds__(256, 2)
void hmma_gemm(const __nv_bfloat16* __restrict__ Ah, const __nv_bfloat16* __restrict__ Al, int lda,
               const __nv_bfloat16* __restrict__ Bh, const __nv_bfloat16* __restrict__ Bl, int ldb,
               float* __restrict__ C, __nv_bfloat16* __restrict__ Chi,
               __nv_bfloat16* __restrict__ Clo, int ldc,
               int N, int K, const float* __restrict__ bias, size_t part_stride)
{
    extern __shared__ char smem[];
    const uint32_t su = (uint32_t)__cvta_generic_to_shared(smem);

    const int tid  = threadIdx.x;
    const int wid  = tid >> 5;
    const int lane = tid & 31;
    const int bm = blockIdx.y * 128;
    const int bn = blockIdx.x * 64;
    const int warp_m = wid & 3;
    const int warp_n = wid >> 2;         // 0..1
    const int b_rows = min(64, N - bn);

    const int nch_total = K >> 5;
    const int per = nch_total / gridDim.z;
    const int c_begin = blockIdx.z * per;
    const int c_end   = c_begin + per;
    if (gridDim.z > 1) C += (size_t)blockIdx.z * part_stride;

    float acc[2][4][4];
    #pragma unroll
    for (int i = 0; i < 2; i++)
        #pragma unroll
        for (int j = 0; j < 4; j++)
            #pragma unroll
            for (int q = 0; q < 4; q++) acc[i][j][q] = 0.f;

    auto issue_stage = [&](int stg, int k0) {
        const uint32_t sb = su + (uint32_t)(stg * STAGE_B);
        // A: 512 (row, c16) pairs over 2 iterations
        #pragma unroll
        for (int i = 0; i < 2; i++) {
            const int id  = tid + i * 256;
            const int r   = id >> 2;        // 0..127
            const int c16 = id & 3;
            const uint32_t doff = sw32(r, c16);
            const size_t aoff = (size_t)(bm + r) * lda + k0 + (c16 << 3);
            cp16(sb + doff,          Ah + aoff, true);
            cp16(sb + OFF_AL + doff, Al + aoff, true);
        }
        // B: 256 (row, c16) pairs
        {
            const int r   = tid >> 2;       // 0..63
            const int c16 = tid & 3;
            const uint32_t doff = sw32(r, c16);
            const bool v = r < b_rows;
            const size_t boff = (size_t)(bn + (v ? r : 0)) * ldb + k0 + (c16 << 3);
            cp16(sb + OFF_BH + doff, Bh + boff, v);
            cp16(sb + OFF_BL + doff, Bl + boff, v);
        }
        asm volatile("cp.async.commit_group;" ::: "memory");
    };

    const int span = c_end - c_begin;
    issue_stage(0, c_begin << 5);
    if (span > 1) issue_stage(1, (c_begin + 1) << 5);
    if (span > 2) issue_stage(2, (c_begin + 2) << 5);

    const int lrow = lane & 15;
    const int lhalf = lane >> 4;
    const int a_row0 = warp_m * 32 + lrow;
    const int b_row0 = warp_n * 32 + lrow;

    for (int c = c_begin; c < c_end; c++) {
        const int rem = c_end - c - 1;
        if      (rem >= 2) asm volatile("cp.async.wait_group 2;" ::: "memory");
        else if (rem == 1) asm volatile("cp.async.wait_group 1;" ::: "memory");
        else               asm volatile("cp.async.wait_group 0;" ::: "memory");
        __syncthreads();

        // refill the stage consumed two chunks ago (safe after the barrier)
        if (c + 3 < c_end)
            issue_stage((c + 3 - c_begin) & 3, (c + 3) << 5);

        const uint32_t sb = su + (uint32_t)(((c - c_begin) & 3) * STAGE_B);

        #pragma unroll
        for (int ks = 0; ks < 2; ks++) {
            const int kc2 = ks * 2 + lhalf;
            uint32_t ah[2][4], al[2][4];
            #pragma unroll
            for (int mt = 0; mt < 2; mt++) {
                const uint32_t ro = sw32(a_row0 + mt * 16, kc2);
                ldsm_x4(ah[mt], sb + ro);
                ldsm_x4(al[mt], sb + OFF_AL + ro);
            }
            uint32_t bh0[4], bl0[4], bh1[4], bl1[4];
            {
                const uint32_t bo0 = sw32(b_row0, kc2);
                const uint32_t bo1 = sw32(b_row0 + 16, kc2);
                ldsm_x4(bh0, sb + OFF_BH + bo0);
                ldsm_x4(bl0, sb + OFF_BL + bo0);
                ldsm_x4(bh1, sb + OFF_BH + bo1);
                ldsm_x4(bl1, sb + OFF_BL + bo1);
            }
            {
                uint32_t be[2]  = {bh0[0], bh0[2]};
                uint32_t bo2[2] = {bh0[1], bh0[3]};
                uint32_t le[2]  = {bl0[0], bl0[2]};
                uint32_t lo2[2] = {bl0[1], bl0[3]};
                #pragma unroll
                for (int mt = 0; mt < 2; mt++) {
                    mma_bf16(acc[mt][0], ah[mt], be);
                    mma_bf16(acc[mt][0], ah[mt], le);
                    mma_bf16(acc[mt][0], al[mt], be);
                    mma_bf16(acc[mt][1], ah[mt], bo2);
                    mma_bf16(acc[mt][1], ah[mt], lo2);
                    mma_bf16(acc[mt][1], al[mt], bo2);
                }
            }
            {
                uint32_t be[2]  = {bh1[0], bh1[2]};
                uint32_t bo2[2] = {bh1[1], bh1[3]};
                uint32_t le[2]  = {bl1[0], bl1[2]};
                uint32_t lo2[2] = {bl1[1], bl1[3]};
                #pragma unroll
                for (int mt = 0; mt < 2; mt++) {
                    mma_bf16(acc[mt][2], ah[mt], be);
                    mma_bf16(acc[mt][2], ah[mt], le);
                    mma_bf16(acc[mt][2], al[mt], be);
                    mma_bf16(acc[mt][3], ah[mt], bo2);
                    mma_bf16(acc[mt][3], ah[mt], lo2);
                    mma_bf16(acc[mt][3], al[mt], bo2);
                }
            }
        }
    }

    // epilogue
    #pragma unroll
    for (int mt = 0; mt < 2; mt++) {
        const int r0 = bm + warp_m * 32 + mt * 16 + (lane >> 2);
        #pragma unroll
        for (int nt = 0; nt < 4; nt++) {
            const int col = bn + warp_n * 32 + nt * 8 + ((lane & 3) << 1);
            if (col < N) {
                float v[4];
                #pragma unroll
                for (int q = 0; q < 4; q++) {
                    float val = acc[mt][nt][q];
                    if (EPI == 1) {
                        val += bias[col + (q & 1)];
                        val = fmaxf(val, 0.f) + log1pf(__expf(-fabsf(val)));
                    }
                    if (EPI == 2) {
                        val += bias[col + (q & 1)];
                        val = val / (1.f + __expf(-val));
                    }
                    v[q] = val;
                }
                if (F32S) {
                    *reinterpret_cast<float2*>(&C[(size_t)r0 * ldc + col]) = make_float2(v[0], v[1]);
                    *reinterpret_cast<float2*>(&C[(size_t)(r0 + 8) * ldc + col]) = make_float2(v[2], v[3]);
                }
                if (HLS) {
                    *reinterpret_cast<uint32_t*>(&Chi[(size_t)r0 * ldc + col])       = pack_hi(v[0], v[1]);
                    *reinterpret_cast<uint32_t*>(&Clo[(size_t)r0 * ldc + col])       = pack_lo(v[0], v[1]);
                    *reinterpret_cast<uint32_t*>(&Chi[(size_t)(r0 + 8) * ldc + col]) = pack_hi(v[2], v[3]);
                    *reinterpret_cast<uint32_t*>(&Clo[(size_t)(r0 + 8) * ldc + col]) = pack_lo(v[2], v[3]);
                }
            }
        }
    }
}

// ---------------- split-K reduction for x_dbl ----------------
__global__ __launch_bounds__(256)
void reduce_xdbl_kernel()
{
    int i = blockIdx.x * blockDim.x + threadIdx.x;
    if (i >= MM * NXD) return;
    float s = 0.f;
    #pragma unroll
    for (int z = 0; z < 8; z++) s += g_part[(size_t)z * MM * NXD + i];
    g_xdbl[i] = s;
    __nv_bfloat16 h = __float2bfloat16_rn(s);
    g_xd_hi[i] = h;
    g_xd_lo[i] = __float2bfloat16_rn(s - __bfloat162float(h));
}

// ---------------- causal depthwise conv(4) + SiLU, 4 timesteps/thread ----------------
__global__ __launch_bounds__(256)
void conv_silu_kernel(const float* __restrict__ w, const float* __restrict__ bias)
{
    int idx = blockIdx.x * blockDim.x + threadIdx.x;
    if (idx >= MM * DI / 4) return;
    const int d  = idx & (DI - 1);
    const int g  = idx >> 11;
    const int b  = g >> 9;
    const int l0 = (g & 511) << 2;
    const int m0 = b * LL + l0;

    const float w0 = w[d*4+0], w1 = w[d*4+1], w2 = w[d*4+2], w3 = w[d*4+3];
    const float bs = bias[d];
    const float* base = g_xz + (size_t)m0 * (2 * DI) + d;
    const ptrdiff_t rs = 2 * DI;

    float v[7];
    v[0] = (l0 >= 3) ? base[-3 * rs] : 0.f;
    v[1] = (l0 >= 2) ? base[-2 * rs] : 0.f;
    v[2] = (l0 >= 1) ? base[-1 * rs] : 0.f;
    v[3] = base[0];
    v[4] = base[1 * rs];
    v[5] = base[2 * rs];
    v[6] = base[3 * rs];

    #pragma unroll
    for (int t = 0; t < 4; t++) {
        float acc = bs;
        acc = fmaf(v[t],     w0, acc);
        acc = fmaf(v[t + 1], w1, acc);
        acc = fmaf(v[t + 2], w2, acc);
        acc = fmaf(v[t + 3], w3, acc);
        const float sig = 1.f / (1.f + __expf(-acc));
        const float r = acc * sig;
        const size_t o = (size_t)(m0 + t) * DI + d;
        g_xc[o] = r;
        __nv_bfloat16 h = __float2bfloat16_rn(r);
        g_xc_hi[o] = h;
        g_xc_lo[o] = __float2bfloat16_rn(r - __bfloat162float(h));
    }
}

// ---------------- parallel scan: Pass A ----------------
__global__ __launch_bounds__(256)
void scanA_kernel(const float* __restrict__ A_log)
{
    const int tid  = threadIdx.x;
    const int warp = tid >> 5;
    const int lane = tid & 31;
    const int n = lane & 15;
    const int ch = blockIdx.y;
    const int b  = blockIdx.z;
    const int d  = (blockIdx.x << 4) + (warp << 1) + (lane >> 4);

    const float A = -__expf(A_log[d * DS + n]);
    float h = 0.f, P = 1.f;

    const int t0 = ch * CHL;
    const float* pd = g_delta + (size_t)b * LL * DI + (size_t)t0 * DI + d;
    const float* pu = g_xc    + (size_t)b * LL * DI + (size_t)t0 * DI + d;
    const float* pb = g_xdbl  + (size_t)b * LL * NXD + (size_t)t0 * NXD + DR + n;

    #pragma unroll 4
    for (int t = 0; t < CHL; t++) {
        const float delta = __ldg(pd);
        const float u     = __ldg(pu);
        const float Bn    = __ldg(pb);
        const float e = __expf(delta * A);
        h = fmaf(e, h, delta * u * Bn);
        P *= e;
        pd += DI; pu += DI; pb += NXD;
    }
    const size_t o = ((size_t)(b * NCH + ch) * DI + d) * DS + n;
    gA_P[o] = P;
    gA_h[o] = h;
}

// ---------------- Pass B ----------------
__global__ __launch_bounds__(256)
void scanB_kernel()
{
    int i = blockIdx.x * blockDim.x + threadIdx.x;
    if (i >= BB * DI * DS) return;
    const int b = i / (DI * DS);
    const int r = i % (DI * DS);
    float h = 0.f;
    #pragma unroll
    for (int ch = 0; ch < NCH; ch++) {
        const size_t o = (size_t)(b * NCH + ch) * DI * DS + r;
        gB_in[o] = h;
        h = gA_P[o] * h + gA_h[o];
    }
}

// ---------------- Pass C ----------------
__global__ __launch_bounds__(256)
void scanC_kernel(const float* __restrict__ A_log, const float* __restrict__ Dvec)
{
    const int tid  = threadIdx.x;
    const int warp = tid >> 5;
    const int lane = tid & 31;
    const int n = lane & 15;
    const int ch = blockIdx.y;
    const int b  = blockIdx.z;
    const int d  = (blockIdx.x << 4) + (warp << 1) + (lane >> 4);

    const float A  = -__expf(A_log[d * DS + n]);
    const float Dd = Dvec[d];
    float h = gB_in[((size_t)(b * NCH + ch) * DI + d) * DS + n];

    const int t0 = ch * CHL;
    const float* pd = g_delta + (size_t)b * LL * DI + (size_t)t0 * DI + d;
    const float* pu = g_xc    + (size_t)b * LL * DI + (size_t)t0 * DI + d;
    const float* pz = g_xz    + (size_t)b * LL * (2 * DI) + (size_t)t0 * (2 * DI) + DI + d;
    const float* pb = g_xdbl  + (size_t)b * LL * NXD + (size_t)t0 * NXD + DR + n;
    size_t       oy = (size_t)b * LL * DI + (size_t)t0 * DI + d;

    #pragma unroll 2
    for (int t = 0; t < CHL; t++) {
        const float delta = __ldg(pd);
        const float u     = __ldg(pu);
        const float Bn    = __ldg(pb);
        const float Cn    = __ldg(pb + DS);

        const float e = __expf(delta * A);
        h = fmaf(e, h, delta * u * Bn);

        float p = h * Cn;
        p += __shfl_xor_sync(0xffffffffu, p, 1);
        p += __shfl_xor_sync(0xffffffffu, p, 2);
        p += __shfl_xor_sync(0xffffffffu, p, 4);
        p += __shfl_xor_sync(0xffffffffu, p, 8);

        if (n == 0) {
            const float z = __ldg(pz);
            const float sig = 1.f / (1.f + __expf(-z));
            const float val = (p + Dd * u) * (z * sig);
            __nv_bfloat16 hh = __float2bfloat16_rn(val);
            g_y_hi[oy] = hh;
            g_y_lo[oy] = __float2bfloat16_rn(val - __bfloat162float(hh));
        }
        pd += DI; pu += DI; pz += 2 * DI; pb += NXD; oy += DI;
    }
}

// ---------------- launch ----------------
extern "C" void kernel_launch(void* const* d_in, const int* in_sizes, int n_in,
                              void* d_out, int out_size)
{
    const float* x         = (const float*)d_in[0];
    const float* in_proj_w = (const float*)d_in[1];
    const float* conv_w    = (const float*)d_in[2];
    const float* conv_b    = (const float*)d_in[3];
    const float* x_proj_w  = (const float*)d_in[4];
    const float* dt_proj_w = (const float*)d_in[5];
    const float* dt_proj_b = (const float*)d_in[6];
    const float* A_log     = (const float*)d_in[7];
    const float* Dv        = (const float*)d_in[8];
    const float* ssm_out_w = (const float*)d_in[9];
    const float* final_w   = (const float*)d_in[10];
    const float* final_b   = (const float*)d_in[11];
    float* out = (float*)d_out;

    float *p_xz, *p_delta, *p_part;
    __nv_bfloat16 *x_hi, *x_lo, *w1_hi, *w1_lo, *wx_hi, *wx_lo, *wd_hi, *wd_lo;
    __nv_bfloat16 *wo_hi, *wo_lo, *wf_hi, *wf_lo, *xc_hi, *xc_lo, *xd_hi, *xd_lo;
    __nv_bfloat16 *y_hi, *y_lo, *o1_hi, *o1_lo;
    cudaGetSymbolAddress((void**)&p_xz, g_xz);
    cudaGetSymbolAddress((void**)&p_delta, g_delta);
    cudaGetSymbolAddress((void**)&p_part, g_part);
    cudaGetSymbolAddress((void**)&x_hi, g_x_hi);     cudaGetSymbolAddress((void**)&x_lo, g_x_lo);
    cudaGetSymbolAddress((void**)&w1_hi, g_w1_hi);   cudaGetSymbolAddress((void**)&w1_lo, g_w1_lo);
    cudaGetSymbolAddress((void**)&wx_hi, g_wx_hi);   cudaGetSymbolAddress((void**)&wx_lo, g_wx_lo);
    cudaGetSymbolAddress((void**)&wd_hi, g_wd_hi);   cudaGetSymbolAddress((void**)&wd_lo, g_wd_lo);
    cudaGetSymbolAddress((void**)&wo_hi, g_wo_hi);   cudaGetSymbolAddress((void**)&wo_lo, g_wo_lo);
    cudaGetSymbolAddress((void**)&wf_hi, g_wf_hi);   cudaGetSymbolAddress((void**)&wf_lo, g_wf_lo);
    cudaGetSymbolAddress((void**)&xc_hi, g_xc_hi);   cudaGetSymbolAddress((void**)&xc_lo, g_xc_lo);
    cudaGetSymbolAddress((void**)&xd_hi, g_xd_hi);   cudaGetSymbolAddress((void**)&xd_lo, g_xd_lo);
    cudaGetSymbolAddress((void**)&y_hi, g_y_hi);     cudaGetSymbolAddress((void**)&y_lo, g_y_lo);
    cudaGetSymbolAddress((void**)&o1_hi, g_o1_hi);   cudaGetSymbolAddress((void**)&o1_lo, g_o1_lo);

    cudaFuncSetAttribute(hmma_gemm<0,true,false>,  cudaFuncAttributeMaxDynamicSharedMemorySize, SMEM_B);
    cudaFuncSetAttribute(hmma_gemm<1,true,false>,  cudaFuncAttributeMaxDynamicSharedMemorySize, SMEM_B);
    cudaFuncSetAttribute(hmma_gemm<0,false,true>,  cudaFuncAttributeMaxDynamicSharedMemorySize, SMEM_B);
    cudaFuncSetAttribute(hmma_gemm<2,true,false>,  cudaFuncAttributeMaxDynamicSharedMemorySize, SMEM_B);

    // (1) split x   (2) split in_proj_w   (3) split remaining weights
    split4_kernel<<<(MM*DM/4 + 255)/256, 256>>>((const float4*)x, (uint2*)x_hi, (uint2*)x_lo, MM*DM/4);
    split4_kernel<<<(2*DI*DM/4 + 255)/256, 256>>>((const float4*)in_proj_w, (uint2*)w1_hi, (uint2*)w1_lo, 2*DI*DM/4);
    {
        int n0 = NXD*DI/4, n1 = DI*DR/4, n2 = DM*DI/4, n3 = DM*DM/4;
        split_rest_kernel<<<(n0+n1+n2+n3 + 255)/256, 256>>>(
            (const float4*)x_proj_w,  (uint2*)wx_hi, (uint2*)wx_lo, n0,
            (const float4*)dt_proj_w, (uint2*)wd_hi, (uint2*)wd_lo, n1,
            (const float4*)ssm_out_w, (uint2*)wo_hi, (uint2*)wo_lo, n2,
            (const float4*)final_w,   (uint2*)wf_hi, (uint2*)wf_lo, n3);
    }

    // (4) G1: in_proj -> g_xz (f32)   [profiled launch]
    hmma_gemm<0,true,false><<<dim3(64,32,1), 256, SMEM_B>>>(
        x_hi, x_lo, DM, w1_hi, w1_lo, DM, p_xz, nullptr, nullptr, 2*DI, 2*DI, DM, nullptr, 0);

    // (5) conv + SiLU -> xc f32 + hi/lo
    conv_silu_kernel<<<(MM * DI / 4) / 256, 256>>>(conv_w, conv_b);

    // (6) G3a split-K x8: partials = xc @ x_proj_w^T
    hmma_gemm<0,true,false><<<dim3(2,32,8), 256, SMEM_B>>>(
        xc_hi, xc_lo, DI, wx_hi, wx_lo, DI, p_part, nullptr, nullptr, NXD, NXD, DI, nullptr,
        (size_t)MM * NXD);

    // (7) reduce partials -> x_dbl f32 + hi/lo
    reduce_xdbl_kernel<<<(MM*NXD + 255)/256, 256>>>();

    // (8) G3b: delta = softplus(dt @ dt_proj_w^T + b) -> f32
    hmma_gemm<1,true,false><<<dim3(32,32,1), 256, SMEM_B>>>(
        xd_hi, xd_lo, NXD, wd_hi, wd_lo, DR, p_delta, nullptr, nullptr, DI, DI, DR, dt_proj_b, 0);

    // (9-11) parallel scan
    scanA_kernel<<<dim3(128, NCH, BB), 256>>>(A_log);
    scanB_kernel<<<(BB*DI*DS + 255)/256, 256>>>();
    scanC_kernel<<<dim3(128, NCH, BB), 256>>>(A_log, Dv);

    // (12) G5: out_proj -> o1 hi/lo
    hmma_gemm<0,false,true><<<dim3(16,32,1), 256, SMEM_B>>>(
        y_hi, y_lo, DI, wo_hi, wo_lo, DI, nullptr, o1_hi, o1_lo, DM, DM, DI, nullptr, 0);

    // (13) G6: out = silu(o1 @ final_w^T + b)
    hmma_gemm<2,true,false><<<dim3(16,32,1), 256, SMEM_B>>>(
        o1_hi, o1_lo, DM, wf_hi, wf_lo, DM, out, nullptr, nullptr, DM, DM, DM, final_b, 0);
}

// round 14
// speedup vs baseline: 1.0685x; 1.0685x over previous
#include <cuda_runtime.h>
#include <cuda_bf16.h>
#include <cstdint>
#include <math.h>

#define BB 2
#define LL 2048
#define DM 1024
#define DI 2048
#define DS 16
#define DR 64
#define NXD 96          // DR + 2*DS
#define MM (BB*LL)      // 4096

#define NCH   32        // time chunks for parallel scan
#define CHL   64        // chunk length (NCH*CHL == LL)

// CTA tile 128(M) x 64(N), BK=64. Stage: Ah,Al (128x64 bf16 =16KB ea) + Bh,Bl (64x64 =8KB ea)
#define OFF_AL   16384
#define OFF_BH   32768
#define OFF_BL   40960
#define STAGE_B  49152
#define SMEM_B   (2 * STAGE_B)   // 98304 -> 2 CTAs/SM

// ---------------- fp32 scratch ----------------
__device__ float g_xz[(size_t)MM * (2*DI)];
__device__ float g_xc[(size_t)MM * DI];
__device__ float g_xdbl[(size_t)MM * NXD];
__device__ float g_delta[(size_t)MM * DI];
__device__ float g_part[(size_t)8 * MM * NXD];   // split-K partials for G3a

// parallel-scan chunk state: [b][ch][d][n]
__device__ float gA_P [(size_t)BB * NCH * DI * DS];
__device__ float gA_h [(size_t)BB * NCH * DI * DS];
__device__ float gB_in[(size_t)BB * NCH * DI * DS];

// ---------------- bf16 hi/lo operand buffers ----------------
__device__ __nv_bfloat16 g_x_hi [(size_t)MM * DM],     g_x_lo [(size_t)MM * DM];
__device__ __nv_bfloat16 g_w1_hi[(size_t)2*DI * DM],   g_w1_lo[(size_t)2*DI * DM];
__device__ __nv_bfloat16 g_wx_hi[(size_t)NXD * DI],    g_wx_lo[(size_t)NXD * DI];
__device__ __nv_bfloat16 g_wd_hi[(size_t)DI * DR],     g_wd_lo[(size_t)DI * DR];
__device__ __nv_bfloat16 g_wf_hi[(size_t)DM * DM],     g_wf_lo[(size_t)DM * DM];
__device__ __nv_bfloat16 g_woT_hi[(size_t)DI * DM],    g_woT_lo[(size_t)DI * DM];   // ssm_out_w^T
__device__ __nv_bfloat16 g_wfo_hi[(size_t)DM * DI],    g_wfo_lo[(size_t)DM * DI];   // final_w @ ssm_out_w
__device__ __nv_bfloat16 g_xc_hi[(size_t)MM * DI],     g_xc_lo[(size_t)MM * DI];
__device__ __nv_bfloat16 g_xd_hi[(size_t)MM * NXD],    g_xd_lo[(size_t)MM * NXD];
__device__ __nv_bfloat16 g_y_hi [(size_t)MM * DI],     g_y_lo [(size_t)MM * DI];

// ---------------- helpers ----------------
__device__ __forceinline__ void mma_bf16(float* c, const uint32_t* a, const uint32_t* b) {
    asm volatile(
        "mma.sync.aligned.m16n8k16.row.col.f32.bf16.bf16.f32 "
        "{%0,%1,%2,%3}, {%4,%5,%6,%7}, {%8,%9}, {%0,%1,%2,%3};"
        : "+f"(c[0]), "+f"(c[1]), "+f"(c[2]), "+f"(c[3])
        : "r"(a[0]), "r"(a[1]), "r"(a[2]), "r"(a[3]), "r"(b[0]), "r"(b[1]));
}
__device__ __forceinline__ void ldsm_x4(uint32_t* r, uint32_t addr) {
    asm volatile("ldmatrix.sync.aligned.m8n8.x4.shared.b16 {%0,%1,%2,%3}, [%4];"
        : "=r"(r[0]), "=r"(r[1]), "=r"(r[2]), "=r"(r[3]) : "r"(addr));
}
__device__ __forceinline__ void cp16(uint32_t dst, const void* src, bool valid) {
    int sz = valid ? 16 : 0;
    asm volatile("cp.async.cg.shared.global [%0], [%1], 16, %2;"
        :: "r"(dst), "l"(src), "r"(sz));
}
__device__ __forceinline__ uint32_t pack_hi(float a, float b) {
    __nv_bfloat16 h0 = __float2bfloat16_rn(a), h1 = __float2bfloat16_rn(b);
    return (uint32_t)__bfloat16_as_ushort(h0) | ((uint32_t)__bfloat16_as_ushort(h1) << 16);
}
__device__ __forceinline__ uint32_t pack_lo(float a, float b) {
    __nv_bfloat16 h0 = __float2bfloat16_rn(a), h1 = __float2bfloat16_rn(b);
    float r0 = a - __bfloat162float(h0), r1 = b - __bfloat162float(h1);
    __nv_bfloat16 l0 = __float2bfloat16_rn(r0), l1 = __float2bfloat16_rn(r1);
    return (uint32_t)__bfloat16_as_ushort(l0) | ((uint32_t)__bfloat16_as_ushort(l1) << 16);
}
__device__ __forceinline__ uint32_t sw_off(int r, int c16) {
    return (uint32_t)(r * 128 + ((c16 ^ (r & 7)) << 4));
}

// ---------------- split fp32 -> bf16 hi/lo ----------------
__global__ __launch_bounds__(256)
void split4_kernel(const float4* __restrict__ src, uint2* __restrict__ hi,
                   uint2* __restrict__ lo, int n4)
{
    int i = blockIdx.x * blockDim.x + threadIdx.x;
    if (i >= n4) return;
    float4 v = src[i];
    hi[i] = make_uint2(pack_hi(v.x, v.y), pack_hi(v.z, v.w));
    lo[i] = make_uint2(pack_lo(v.x, v.y), pack_lo(v.z, v.w));
}

__global__ __launch_bounds__(256)
void split_rest_kernel(const float4* s0, uint2* h0, uint2* l0, int n0,
                       const float4* s1, uint2* h1, uint2* l1, int n1,
                       const float4* s2, uint2* h2, uint2* l2, int n2)
{
    int i = blockIdx.x * blockDim.x + threadIdx.x;
    const float4* s; uint2 *h, *l; int j;
    if (i < n0)                { s = s0; h = h0; l = l0; j = i; }
    else if (i < n0+n1)        { s = s1; h = h1; l = l1; j = i - n0; }
    else if (i < n0+n1+n2)     { s = s2; h = h2; l = l2; j = i - n0 - n1; }
    else return;
    float4 v = s[j];
    h[j] = make_uint2(pack_hi(v.x, v.y), pack_hi(v.z, v.w));
    l[j] = make_uint2(pack_lo(v.x, v.y), pack_lo(v.z, v.w));
}

// ---------------- transpose + split: woT[d][m] = ssm_out_w[m][d] ----------------
// src [R=1024, C=2048] f32 -> hiT/loT [C, R] bf16
__global__ __launch_bounds__(256)
void transpose_split_kernel(const float* __restrict__ src,
                            __nv_bfloat16* __restrict__ hiT,
                            __nv_bfloat16* __restrict__ loT,
                            int R, int C)
{
    __shared__ float tile[32][33];
    const int c0 = blockIdx.x * 32;
    const int r0 = blockIdx.y * 32;
    const int tx = threadIdx.x & 31;
    const int ty = threadIdx.x >> 5;     // 0..7
    #pragma unroll
    for (int i = 0; i < 4; i++) {
        int r = r0 + ty + i * 8;
        tile[ty + i * 8][tx] = src[(size_t)r * C + c0 + tx];
    }
    __syncthreads();
    #pragma unroll
    for (int i = 0; i < 4; i++) {
        int dof = ty + i * 8;                        // d offset within tile
        float v = tile[tx][dof];                     // src[r0+tx][c0+dof]
        __nv_bfloat16 h = __float2bfloat16_rn(v);
        const size_t o = (size_t)(c0 + dof) * R + r0 + tx;
        hiT[o] = h;
        loT[o] = __float2bfloat16_rn(v - __bfloat162float(h));
    }
}

// ================= HMMA GEMM: C[M,N] = A[M,K] * B[N,K]^T  (R12 config) =================
// bf16x3 split. CTA 128x64, 256 threads, 8 warps (warptile 32x32), BK=64,
// 2-stage cp.async pipeline, 2 CTAs/SM.
template<int EPI, bool F32S, bool HLS>
__global__ __launch_bounds__(256, 2)
void hmma_gemm(const __nv_bfloat16* __restrict__ Ah, const __nv_bfloat16* __restrict__ Al, int lda,
               const __nv_bfloat16* __restrict__ Bh, const __nv_bfloat16* __restrict__ Bl, int ldb,
               float* __restrict__ C, __nv_bfloat16* __restrict__ Chi,
               __nv_bfloat16* __restrict__ Clo, int ldc,
               int N, int K, const float* __restrict__ bias, size_t part_stride)
{
    extern __shared__ char smem[];
    const uint32_t su = (uint32_t)__cvta_generic_to_shared(smem);

    const int tid  = threadIdx.x;
    const int wid  = tid >> 5;
    const int lane = tid & 31;
    const int bm = blockIdx.y * 128;
    const int bn = blockIdx.x * 64;
    const int warp_m = wid & 3;
    const int warp_n = wid >> 2;
    const int b_rows = min(64, N - bn);

    const int nch_total = K >> 6;
    const int per = nch_total / gridDim.z;
    const int c_begin = blockIdx.z * per;
    const int c_end   = c_begin + per;
    if (gridDim.z > 1) C += (size_t)blockIdx.z * part_stride;

    float acc[2][4][4];
    #pragma unroll
    for (int i = 0; i < 2; i++)
        #pragma unroll
        for (int j = 0; j < 4; j++)
            #pragma unroll
            for (int q = 0; q < 4; q++) acc[i][j][q] = 0.f;

    auto issue_stage = [&](int stg, int k0) {
        const uint32_t sb = su + (uint32_t)(stg * STAGE_B);
        #pragma unroll
        for (int i = 0; i < 4; i++) {
            const int id  = tid + i * 256;
            const int r   = id >> 3;
            const int c16 = id & 7;
            const uint32_t doff = sw_off(r, c16);
            const size_t aoff = (size_t)(bm + r) * lda + k0 + (c16 << 3);
            cp16(sb + doff,          Ah + aoff, true);
            cp16(sb + OFF_AL + doff, Al + aoff, true);
        }
        #pragma unroll
        for (int i = 0; i < 2; i++) {
            const int id  = tid + i * 256;
            const int r   = id >> 3;
            const int c16 = id & 7;
            const uint32_t doff = sw_off(r, c16);
            const bool v = r < b_rows;
            const size_t boff = (size_t)(bn + (v ? r : 0)) * ldb + k0 + (c16 << 3);
            cp16(sb + OFF_BH + doff, Bh + boff, v);
            cp16(sb + OFF_BL + doff, Bl + boff, v);
        }
        asm volatile("cp.async.commit_group;" ::: "memory");
    };

    const int span = c_end - c_begin;
    issue_stage(0, c_begin << 6);
    if (span > 1) issue_stage(1, (c_begin + 1) << 6);

    const int lrow = lane & 15;
    const int lhalf = lane >> 4;
    const int a_row0 = warp_m * 32 + lrow;
    const int b_row0 = warp_n * 32 + lrow;

    for (int c = c_begin; c < c_end; c++) {
        if (c + 1 < c_end) asm volatile("cp.async.wait_group 1;" ::: "memory");
        else               asm volatile("cp.async.wait_group 0;" ::: "memory");
        __syncthreads();

        const uint32_t sb = su + (uint32_t)(((c - c_begin) & 1) * STAGE_B);

        uint32_t ah[2][2][4], al[2][2][4];
        {
            const int kc2 = lhalf;
            #pragma unroll
            for (int mt = 0; mt < 2; mt++) {
                const uint32_t ro = sw_off(a_row0 + mt * 16, kc2);
                ldsm_x4(ah[0][mt], sb + ro);
                ldsm_x4(al[0][mt], sb + OFF_AL + ro);
            }
        }

        #pragma unroll
        for (int ks = 0; ks < 4; ks++) {
            const int cur = ks & 1;
            const int kc2 = ks * 2 + lhalf;
            uint32_t bh0[4], bl0[4], bh1[4], bl1[4];
            {
                const uint32_t bo0 = sw_off(b_row0, kc2);
                const uint32_t bo1 = sw_off(b_row0 + 16, kc2);
                ldsm_x4(bh0, sb + OFF_BH + bo0);
                ldsm_x4(bl0, sb + OFF_BL + bo0);
                ldsm_x4(bh1, sb + OFF_BH + bo1);
                ldsm_x4(bl1, sb + OFF_BL + bo1);
            }
            if (ks < 3) {
                const int kn = (ks + 1) * 2 + lhalf;
                #pragma unroll
                for (int mt = 0; mt < 2; mt++) {
                    const uint32_t ro = sw_off(a_row0 + mt * 16, kn);
                    ldsm_x4(ah[cur ^ 1][mt], sb + ro);
                    ldsm_x4(al[cur ^ 1][mt], sb + OFF_AL + ro);
                }
            }
            {
                uint32_t be[2]  = {bh0[0], bh0[2]};
                uint32_t bo2[2] = {bh0[1], bh0[3]};
                uint32_t le[2]  = {bl0[0], bl0[2]};
                uint32_t lo2[2] = {bl0[1], bl0[3]};
                #pragma unroll
                for (int mt = 0; mt < 2; mt++) {
                    mma_bf16(acc[mt][0], ah[cur][mt], be);
                    mma_bf16(acc[mt][0], ah[cur][mt], le);
                    mma_bf16(acc[mt][0], al[cur][mt], be);
                    mma_bf16(acc[mt][1], ah[cur][mt], bo2);
                    mma_bf16(acc[mt][1], ah[cur][mt], lo2);
                    mma_bf16(acc[mt][1], al[cur][mt], bo2);
                }
            }
            {
                uint32_t be[2]  = {bh1[0], bh1[2]};
                uint32_t bo2[2] = {bh1[1], bh1[3]};
                uint32_t le[2]  = {bl1[0], bl1[2]};
                uint32_t lo2[2] = {bl1[1], bl1[3]};
                #pragma unroll
                for (int mt = 0; mt < 2; mt++) {
                    mma_bf16(acc[mt][2], ah[cur][mt], be);
                    mma_bf16(acc[mt][2], ah[cur][mt], le);
                    mma_bf16(acc[mt][2], al[cur][mt], be);
                    mma_bf16(acc[mt][3], ah[cur][mt], bo2);
                    mma_bf16(acc[mt][3], ah[cur][mt], lo2);
                    mma_bf16(acc[mt][3], al[cur][mt], bo2);
                }
            }
        }
        __syncthreads();
        if (c + 2 < c_end)
            issue_stage((c - c_begin) & 1, (c + 2) << 6);
    }

    // epilogue
    #pragma unroll
    for (int mt = 0; mt < 2; mt++) {
        const int r0 = bm + warp_m * 32 + mt * 16 + (lane >> 2);
        #pragma unroll
        for (int nt = 0; nt < 4; nt++) {
            const int col = bn + warp_n * 32 + nt * 8 + ((lane & 3) << 1);
            if (col < N) {
                float v[4];
                #pragma unroll
                for (int q = 0; q < 4; q++) {
                    float val = acc[mt][nt][q];
                    if (EPI == 1) {
                        val += bias[col + (q & 1)];
                        val = fmaxf(val, 0.f) + log1pf(__expf(-fabsf(val)));
                    }
                    if (EPI == 2) {
                        val += bias[col + (q & 1)];
                        val = val / (1.f + __expf(-val));
                    }
                    v[q] = val;
                }
                if (F32S) {
                    *reinterpret_cast<float2*>(&C[(size_t)r0 * ldc + col]) = make_float2(v[0], v[1]);
                    *reinterpret_cast<float2*>(&C[(size_t)(r0 + 8) * ldc + col]) = make_float2(v[2], v[3]);
                }
                if (HLS) {
                    *reinterpret_cast<uint32_t*>(&Chi[(size_t)r0 * ldc + col])       = pack_hi(v[0], v[1]);
                    *reinterpret_cast<uint32_t*>(&Clo[(size_t)r0 * ldc + col])       = pack_lo(v[0], v[1]);
                    *reinterpret_cast<uint32_t*>(&Chi[(size_t)(r0 + 8) * ldc + col]) = pack_hi(v[2], v[3]);
                    *reinterpret_cast<uint32_t*>(&Clo[(size_t)(r0 + 8) * ldc + col]) = pack_lo(v[2], v[3]);
                }
            }
        }
    }
}

// ---------------- split-K reduction for x_dbl ----------------
__global__ __launch_bounds__(256)
void reduce_xdbl_kernel()
{
    int i = blockIdx.x * blockDim.x + threadIdx.x;
    if (i >= MM * NXD) return;
    float s = 0.f;
    #pragma unroll
    for (int z = 0; z < 8; z++) s += g_part[(size_t)z * MM * NXD + i];
    g_xdbl[i] = s;
    __nv_bfloat16 h = __float2bfloat16_rn(s);
    g_xd_hi[i] = h;
    g_xd_lo[i] = __float2bfloat16_rn(s - __bfloat162float(h));
}

// ---------------- causal depthwise conv(4) + SiLU, 4 timesteps/thread ----------------
__global__ __launch_bounds__(256)
void conv_silu_kernel(const float* __restrict__ w, const float* __restrict__ bias)
{
    int idx = blockIdx.x * blockDim.x + threadIdx.x;
    if (idx >= MM * DI / 4) return;
    const int d  = idx & (DI - 1);
    const int g  = idx >> 11;
    const int b  = g >> 9;
    const int l0 = (g & 511) << 2;
    const int m0 = b * LL + l0;

    const float w0 = w[d*4+0], w1 = w[d*4+1], w2 = w[d*4+2], w3 = w[d*4+3];
    const float bs = bias[d];
    const float* base = g_xz + (size_t)m0 * (2 * DI) + d;
    const ptrdiff_t rs = 2 * DI;

    float v[7];
    v[0] = (l0 >= 3) ? base[-3 * rs] : 0.f;
    v[1] = (l0 >= 2) ? base[-2 * rs] : 0.f;
    v[2] = (l0 >= 1) ? base[-1 * rs] : 0.f;
    v[3] = base[0];
    v[4] = base[1 * rs];
    v[5] = base[2 * rs];
    v[6] = base[3 * rs];

    #pragma unroll
    for (int t = 0; t < 4; t++) {
        float acc = bs;
        acc = fmaf(v[t],     w0, acc);
        acc = fmaf(v[t + 1], w1, acc);
        acc = fmaf(v[t + 2], w2, acc);
        acc = fmaf(v[t + 3], w3, acc);
        const float sig = 1.f / (1.f + __expf(-acc));
        const float r = acc * sig;
        const size_t o = (size_t)(m0 + t) * DI + d;
        g_xc[o] = r;
        __nv_bfloat16 h = __float2bfloat16_rn(r);
        g_xc_hi[o] = h;
        g_xc_lo[o] = __float2bfloat16_rn(r - __bfloat162float(h));
    }
}

// ---------------- parallel scan: Pass A ----------------
__global__ __launch_bounds__(256)
void scanA_kernel(const float* __restrict__ A_log)
{
    const int tid  = threadIdx.x;
    const int warp = tid >> 5;
    const int lane = tid & 31;
    const int n = lane & 15;
    const int ch = blockIdx.y;
    const int b  = blockIdx.z;
    const int d  = (blockIdx.x << 4) + (warp << 1) + (lane >> 4);

    const float A = -__expf(A_log[d * DS + n]);
    float h = 0.f, P = 1.f;

    const int t0 = ch * CHL;
    const float* pd = g_delta + (size_t)b * LL * DI + (size_t)t0 * DI + d;
    const float* pu = g_xc    + (size_t)b * LL * DI + (size_t)t0 * DI + d;
    const float* pb = g_xdbl  + (size_t)b * LL * NXD + (size_t)t0 * NXD + DR + n;

    #pragma unroll 4
    for (int t = 0; t < CHL; t++) {
        const float delta = __ldg(pd);
        const float u     = __ldg(pu);
        const float Bn    = __ldg(pb);
        const float e = __expf(delta * A);
        h = fmaf(e, h, delta * u * Bn);
        P *= e;
        pd += DI; pu += DI; pb += NXD;
    }
    const size_t o = ((size_t)(b * NCH + ch) * DI + d) * DS + n;
    gA_P[o] = P;
    gA_h[o] = h;
}

// ---------------- Pass B ----------------
__global__ __launch_bounds__(256)
void scanB_kernel()
{
    int i = blockIdx.x * blockDim.x + threadIdx.x;
    if (i >= BB * DI * DS) return;
    const int b = i / (DI * DS);
    const int r = i % (DI * DS);
    float h = 0.f;
    #pragma unroll
    for (int ch = 0; ch < NCH; ch++) {
        const size_t o = (size_t)(b * NCH + ch) * DI * DS + r;
        gB_in[o] = h;
        h = gA_P[o] * h + gA_h[o];
    }
}

// ---------------- Pass C ----------------
__global__ __launch_bounds__(256)
void scanC_kernel(const float* __restrict__ A_log, const float* __restrict__ Dvec)
{
    const int tid  = threadIdx.x;
    const int warp = tid >> 5;
    const int lane = tid & 31;
    const int n = lane & 15;
    const int ch = blockIdx.y;
    const int b  = blockIdx.z;
    const int d  = (blockIdx.x << 4) + (warp << 1) + (lane >> 4);

    const float A  = -__expf(A_log[d * DS + n]);
    const float Dd = Dvec[d];
    float h = gB_in[((size_t)(b * NCH + ch) * DI + d) * DS + n];

    const int t0 = ch * CHL;
    const float* pd = g_delta + (size_t)b * LL * DI + (size_t)t0 * DI + d;
    const float* pu = g_xc    + (size_t)b * LL * DI + (size_t)t0 * DI + d;
    const float* pz = g_xz    + (size_t)b * LL * (2 * DI) + (size_t)t0 * (2 * DI) + DI + d;
    const float* pb = g_xdbl  + (size_t)b * LL * NXD + (size_t)t0 * NXD + DR + n;
    size_t       oy = (size_t)b * LL * DI + (size_t)t0 * DI + d;

    #pragma unroll 2
    for (int t = 0; t < CHL; t++) {
        const float delta = __ldg(pd);
        const float u     = __ldg(pu);
        const float Bn    = __ldg(pb);
        const float Cn    = __ldg(pb + DS);

        const float e = __expf(delta * A);
        h = fmaf(e, h, delta * u * Bn);

        float p = h * Cn;
        p += __shfl_xor_sync(0xffffffffu, p, 1);
        p += __shfl_xor_sync(0xffffffffu, p, 2);
        p += __shfl_xor_sync(0xffffffffu, p, 4);
        p += __shfl_xor_sync(0xffffffffu, p, 8);

        if (n == 0) {
            const float z = __ldg(pz);
            const float sig = 1.f / (1.f + __expf(-z));
            const float val = (p + Dd * u) * (z * sig);
            __nv_bfloat16 hh = __float2bfloat16_rn(val);
            g_y_hi[oy] = hh;
            g_y_lo[oy] = __float2bfloat16_rn(val - __bfloat162float(hh));
        }
        pd += DI; pu += DI; pz += 2 * DI; pb += NXD; oy += DI;
    }
}

// ---------------- launch ----------------
extern "C" void kernel_launch(void* const* d_in, const int* in_sizes, int n_in,
                              void* d_out, int out_size)
{
    const float* x         = (const float*)d_in[0];
    const float* in_proj_w = (const float*)d_in[1];
    const float* conv_w    = (const float*)d_in[2];
    const float* conv_b    = (const float*)d_in[3];
    const float* x_proj_w  = (const float*)d_in[4];
    const float* dt_proj_w = (const float*)d_in[5];
    const float* dt_proj_b = (const float*)d_in[6];
    const float* A_log     = (const float*)d_in[7];
    const float* Dv        = (const float*)d_in[8];
    const float* ssm_out_w = (const float*)d_in[9];
    const float* final_w   = (const float*)d_in[10];
    const float* final_b   = (const float*)d_in[11];
    float* out = (float*)d_out;

    float *p_xz, *p_delta, *p_part;
    __nv_bfloat16 *x_hi, *x_lo, *w1_hi, *w1_lo, *wx_hi, *wx_lo, *wd_hi, *wd_lo;
    __nv_bfloat16 *wf_hi, *wf_lo, *woT_hi, *woT_lo, *wfo_hi, *wfo_lo;
    __nv_bfloat16 *xc_hi, *xc_lo, *xd_hi, *xd_lo, *y_hi, *y_lo;
    cudaGetSymbolAddress((void**)&p_xz, g_xz);
    cudaGetSymbolAddress((void**)&p_delta, g_delta);
    cudaGetSymbolAddress((void**)&p_part, g_part);
    cudaGetSymbolAddress((void**)&x_hi, g_x_hi);     cudaGetSymbolAddress((void**)&x_lo, g_x_lo);
    cudaGetSymbolAddress((void**)&w1_hi, g_w1_hi);   cudaGetSymbolAddress((void**)&w1_lo, g_w1_lo);
    cudaGetSymbolAddress((void**)&wx_hi, g_wx_hi);   cudaGetSymbolAddress((void**)&wx_lo, g_wx_lo);
    cudaGetSymbolAddress((void**)&wd_hi, g_wd_hi);   cudaGetSymbolAddress((void**)&wd_lo, g_wd_lo);
    cudaGetSymbolAddress((void**)&wf_hi, g_wf_hi);   cudaGetSymbolAddress((void**)&wf_lo, g_wf_lo);
    cudaGetSymbolAddress((void**)&woT_hi, g_woT_hi); cudaGetSymbolAddress((void**)&woT_lo, g_woT_lo);
    cudaGetSymbolAddress((void**)&wfo_hi, g_wfo_hi); cudaGetSymbolAddress((void**)&wfo_lo, g_wfo_lo);
    cudaGetSymbolAddress((void**)&xc_hi, g_xc_hi);   cudaGetSymbolAddress((void**)&xc_lo, g_xc_lo);
    cudaGetSymbolAddress((void**)&xd_hi, g_xd_hi);   cudaGetSymbolAddress((void**)&xd_lo, g_xd_lo);
    cudaGetSymbolAddress((void**)&y_hi, g_y_hi);     cudaGetSymbolAddress((void**)&y_lo, g_y_lo);

    cudaFuncSetAttribute(hmma_gemm<0,true,false>,  cudaFuncAttributeMaxDynamicSharedMemorySize, SMEM_B);
    cudaFuncSetAttribute(hmma_gemm<1,true,false>,  cudaFuncAttributeMaxDynamicSharedMemorySize, SMEM_B);
    cudaFuncSetAttribute(hmma_gemm<0,false,true>,  cudaFuncAttributeMaxDynamicSharedMemorySize, SMEM_B);
    cudaFuncSetAttribute(hmma_gemm<2,true,false>,  cudaFuncAttributeMaxDynamicSharedMemorySize, SMEM_B);

    // (1) split x   (2) split in_proj_w   (3) split x_proj/dt_proj/final_w
    split4_kernel<<<(MM*DM/4 + 255)/256, 256>>>((const float4*)x, (uint2*)x_hi, (uint2*)x_lo, MM*DM/4);
    split4_kernel<<<(2*DI*DM/4 + 255)/256, 256>>>((const float4*)in_proj_w, (uint2*)w1_hi, (uint2*)w1_lo, 2*DI*DM/4);
    {
        int n0 = NXD*DI/4, n1 = DI*DR/4, n2 = DM*DM/4;
        split_rest_kernel<<<(n0+n1+n2 + 255)/256, 256>>>(
            (const float4*)x_proj_w,  (uint2*)wx_hi, (uint2*)wx_lo, n0,
            (const float4*)dt_proj_w, (uint2*)wd_hi, (uint2*)wd_lo, n1,
            (const float4*)final_w,   (uint2*)wf_hi, (uint2*)wf_lo, n2);
    }

    // (4) G1: in_proj -> g_xz (f32)   [profiled launch]
    hmma_gemm<0,true,false><<<dim3(64,32,1), 256, SMEM_B>>>(
        x_hi, x_lo, DM, w1_hi, w1_lo, DM, p_xz, nullptr, nullptr, 2*DI, 2*DI, DM, nullptr, 0);

    // (5) transpose+split ssm_out_w -> woT [DI, DM]
    transpose_split_kernel<<<dim3(DI/32, DM/32), 256>>>(ssm_out_w, woT_hi, woT_lo, DM, DI);

    // (6) pre-GEMM: Wfo[n,d] = sum_m final_w[n,m] * ssm_out_w[m,d]  -> wfo hi/lo [DM, DI]
    hmma_gemm<0,false,true><<<dim3(DI/64, DM/128, 1), 256, SMEM_B>>>(
        wf_hi, wf_lo, DM, woT_hi, woT_lo, DM, nullptr, wfo_hi, wfo_lo, DI, DI, DM, nullptr, 0);

    // (7) conv + SiLU -> xc f32 + hi/lo
    conv_silu_kernel<<<(MM * DI / 4) / 256, 256>>>(conv_w, conv_b);

    // (8) G3a split-K x8: partials = xc @ x_proj_w^T
    hmma_gemm<0,true,false><<<dim3(2,32,8), 256, SMEM_B>>>(
        xc_hi, xc_lo, DI, wx_hi, wx_lo, DI, p_part, nullptr, nullptr, NXD, NXD, DI, nullptr,
        (size_t)MM * NXD);

    // (9) reduce partials -> x_dbl f32 + hi/lo
    reduce_xdbl_kernel<<<(MM*NXD + 255)/256, 256>>>();

    // (10) G3b: delta = softplus(dt @ dt_proj_w^T + b) -> f32
    hmma_gemm<1,true,false><<<dim3(32,32,1), 256, SMEM_B>>>(
        xd_hi, xd_lo, NXD, wd_hi, wd_lo, DR, p_delta, nullptr, nullptr, DI, DI, DR, dt_proj_b, 0);

    // (11-13) parallel scan
    scanA_kernel<<<dim3(128, NCH, BB), 256>>>(A_log);
    scanB_kernel<<<(BB*DI*DS + 255)/256, 256>>>();
    scanC_kernel<<<dim3(128, NCH, BB), 256>>>(A_log, Dv);

    // (14) fused final: out = silu(y @ Wfo^T + final_b)
    hmma_gemm<2,true,false><<<dim3(DM/64, MM/128, 1), 256, SMEM_B>>>(
        y_hi, y_lo, DI, wfo_hi, wfo_lo, DI, out, nullptr, nullptr, DM, DM, DI, final_b, 0);
}

// round 15
// speedup vs baseline: 1.0762x; 1.0073x over previous
#include <cuda_runtime.h>
#include <cuda_bf16.h>
#include <cstdint>
#include <math.h>

#define BB 2
#define LL 2048
#define DM 1024
#define DI 2048
#define DS 16
#define DR 64
#define NXD 96          // DR + 2*DS
#define MM (BB*LL)      // 4096

#define NCH   32        // time chunks for parallel scan
#define CHL   64        // chunk length (NCH*CHL == LL)

// CTA tile 128(M) x 64(N), BK=64. Stage: Ah,Al (128x64 bf16 =16KB ea) + Bh,Bl (64x64 =8KB ea)
#define OFF_AL   16384
#define OFF_BH   32768
#define OFF_BL   40960
#define STAGE_B  49152
#define SMEM_B   (2 * STAGE_B)   // 98304 -> 2 CTAs/SM

// ---------------- fp32 scratch ----------------
__device__ float g_xz[(size_t)MM * (2*DI)];
__device__ float g_xc[(size_t)MM * DI];
__device__ float g_xdbl[(size_t)MM * NXD];
__device__ float g_delta[(size_t)MM * DI];
__device__ float g_part[(size_t)8 * MM * NXD];   // split-K partials for G3a

// parallel-scan chunk state: [b][ch][d][n]
__device__ float gA_P [(size_t)BB * NCH * DI * DS];
__device__ float gA_h [(size_t)BB * NCH * DI * DS];
__device__ float gB_in[(size_t)BB * NCH * DI * DS];

// ---------------- bf16 hi/lo operand buffers ----------------
__device__ __nv_bfloat16 g_x_hi [(size_t)MM * DM],     g_x_lo [(size_t)MM * DM];
__device__ __nv_bfloat16 g_w1_hi[(size_t)2*DI * DM],   g_w1_lo[(size_t)2*DI * DM];
__device__ __nv_bfloat16 g_wx_hi[(size_t)NXD * DI],    g_wx_lo[(size_t)NXD * DI];
__device__ __nv_bfloat16 g_wd_hi[(size_t)DI * DR],     g_wd_lo[(size_t)DI * DR];
__device__ __nv_bfloat16 g_wf_hi[(size_t)DM * DM],     g_wf_lo[(size_t)DM * DM];
__device__ __nv_bfloat16 g_woT_hi[(size_t)DI * DM],    g_woT_lo[(size_t)DI * DM];   // ssm_out_w^T
__device__ __nv_bfloat16 g_wfo_hi[(size_t)DM * DI],    g_wfo_lo[(size_t)DM * DI];   // final_w @ ssm_out_w
__device__ __nv_bfloat16 g_xc_hi[(size_t)MM * DI],     g_xc_lo[(size_t)MM * DI];
__device__ __nv_bfloat16 g_xd_hi[(size_t)MM * NXD],    g_xd_lo[(size_t)MM * NXD];
__device__ __nv_bfloat16 g_y_hi [(size_t)MM * DI],     g_y_lo [(size_t)MM * DI];

// ---------------- helpers ----------------
__device__ __forceinline__ void mma_bf16(float* c, const uint32_t* a, const uint32_t* b) {
    asm volatile(
        "mma.sync.aligned.m16n8k16.row.col.f32.bf16.bf16.f32 "
        "{%0,%1,%2,%3}, {%4,%5,%6,%7}, {%8,%9}, {%0,%1,%2,%3};"
        : "+f"(c[0]), "+f"(c[1]), "+f"(c[2]), "+f"(c[3])
        : "r"(a[0]), "r"(a[1]), "r"(a[2]), "r"(a[3]), "r"(b[0]), "r"(b[1]));
}
__device__ __forceinline__ void ldsm_x4(uint32_t* r, uint32_t addr) {
    asm volatile("ldmatrix.sync.aligned.m8n8.x4.shared.b16 {%0,%1,%2,%3}, [%4];"
        : "=r"(r[0]), "=r"(r[1]), "=r"(r[2]), "=r"(r[3]) : "r"(addr));
}
__device__ __forceinline__ void cp16(uint32_t dst, const void* src, bool valid) {
    int sz = valid ? 16 : 0;
    asm volatile("cp.async.cg.shared.global [%0], [%1], 16, %2;"
        :: "r"(dst), "l"(src), "r"(sz));
}
__device__ __forceinline__ uint32_t pack_hi(float a, float b) {
    __nv_bfloat16 h0 = __float2bfloat16_rn(a), h1 = __float2bfloat16_rn(b);
    return (uint32_t)__bfloat16_as_ushort(h0) | ((uint32_t)__bfloat16_as_ushort(h1) << 16);
}
__device__ __forceinline__ uint32_t pack_lo(float a, float b) {
    __nv_bfloat16 h0 = __float2bfloat16_rn(a), h1 = __float2bfloat16_rn(b);
    float r0 = a - __bfloat162float(h0), r1 = b - __bfloat162float(h1);
    __nv_bfloat16 l0 = __float2bfloat16_rn(r0), l1 = __float2bfloat16_rn(r1);
    return (uint32_t)__bfloat16_as_ushort(l0) | ((uint32_t)__bfloat16_as_ushort(l1) << 16);
}
__device__ __forceinline__ uint32_t sw_off(int r, int c16) {
    return (uint32_t)(r * 128 + ((c16 ^ (r & 7)) << 4));
}

// ---------------- split fp32 -> bf16 hi/lo ----------------
__global__ __launch_bounds__(256)
void split4_kernel(const float4* __restrict__ src, uint2* __restrict__ hi,
                   uint2* __restrict__ lo, int n4)
{
    int i = blockIdx.x * blockDim.x + threadIdx.x;
    if (i >= n4) return;
    float4 v = src[i];
    hi[i] = make_uint2(pack_hi(v.x, v.y), pack_hi(v.z, v.w));
    lo[i] = make_uint2(pack_lo(v.x, v.y), pack_lo(v.z, v.w));
}

__global__ __launch_bounds__(256)
void split_rest_kernel(const float4* s0, uint2* h0, uint2* l0, int n0,
                       const float4* s1, uint2* h1, uint2* l1, int n1,
                       const float4* s2, uint2* h2, uint2* l2, int n2)
{
    int i = blockIdx.x * blockDim.x + threadIdx.x;
    const float4* s; uint2 *h, *l; int j;
    if (i < n0)                { s = s0; h = h0; l = l0; j = i; }
    else if (i < n0+n1)        { s = s1; h = h1; l = l1; j = i - n0; }
    else if (i < n0+n1+n2)     { s = s2; h = h2; l = l2; j = i - n0 - n1; }
    else return;
    float4 v = s[j];
    h[j] = make_uint2(pack_hi(v.x, v.y), pack_hi(v.z, v.w));
    l[j] = make_uint2(pack_lo(v.x, v.y), pack_lo(v.z, v.w));
}

// ---------------- transpose + split: woT[d][m] = ssm_out_w[m][d] ----------------
__global__ __launch_bounds__(256)
void transpose_split_kernel(const float* __restrict__ src,
                            __nv_bfloat16* __restrict__ hiT,
                            __nv_bfloat16* __restrict__ loT,
                            int R, int C)
{
    __shared__ float tile[32][33];
    const int c0 = blockIdx.x * 32;
    const int r0 = blockIdx.y * 32;
    const int tx = threadIdx.x & 31;
    const int ty = threadIdx.x >> 5;     // 0..7
    #pragma unroll
    for (int i = 0; i < 4; i++) {
        int r = r0 + ty + i * 8;
        tile[ty + i * 8][tx] = src[(size_t)r * C + c0 + tx];
    }
    __syncthreads();
    #pragma unroll
    for (int i = 0; i < 4; i++) {
        int dof = ty + i * 8;
        float v = tile[tx][dof];
        __nv_bfloat16 h = __float2bfloat16_rn(v);
        const size_t o = (size_t)(c0 + dof) * R + r0 + tx;
        hiT[o] = h;
        loT[o] = __float2bfloat16_rn(v - __bfloat162float(h));
    }
}

// ================= HMMA GEMM: C[M,N] = A[M,K] * B[N,K]^T  (R12/R14 config) =================
template<int EPI, bool F32S, bool HLS>
__global__ __launch_bounds__(256, 2)
void hmma_gemm(const __nv_bfloat16* __restrict__ Ah, const __nv_bfloat16* __restrict__ Al, int lda,
               const __nv_bfloat16* __restrict__ Bh, const __nv_bfloat16* __restrict__ Bl, int ldb,
               float* __restrict__ C, __nv_bfloat16* __restrict__ Chi,
               __nv_bfloat16* __restrict__ Clo, int ldc,
               int N, int K, const float* __restrict__ bias, size_t part_stride)
{
    extern __shared__ char smem[];
    const uint32_t su = (uint32_t)__cvta_generic_to_shared(smem);

    const int tid  = threadIdx.x;
    const int wid  = tid >> 5;
    const int lane = tid & 31;
    const int bm = blockIdx.y * 128;
    const int bn = blockIdx.x * 64;
    const int warp_m = wid & 3;
    const int warp_n = wid >> 2;
    const int b_rows = min(64, N - bn);

    const int nch_total = K >> 6;
    const int per = nch_total / gridDim.z;
    const int c_begin = blockIdx.z * per;
    const int c_end   = c_begin + per;
    if (gridDim.z > 1) C += (size_t)blockIdx.z * part_stride;

    float acc[2][4][4];
    #pragma unroll
    for (int i = 0; i < 2; i++)
        #pragma unroll
        for (int j = 0; j < 4; j++)
            #pragma unroll
            for (int q = 0; q < 4; q++) acc[i][j][q] = 0.f;

    auto issue_stage = [&](int stg, int k0) {
        const uint32_t sb = su + (uint32_t)(stg * STAGE_B);
        #pragma unroll
        for (int i = 0; i < 4; i++) {
            const int id  = tid + i * 256;
            const int r   = id >> 3;
            const int c16 = id & 7;
            const uint32_t doff = sw_off(r, c16);
            const size_t aoff = (size_t)(bm + r) * lda + k0 + (c16 << 3);
            cp16(sb + doff,          Ah + aoff, true);
            cp16(sb + OFF_AL + doff, Al + aoff, true);
        }
        #pragma unroll
        for (int i = 0; i < 2; i++) {
            const int id  = tid + i * 256;
            const int r   = id >> 3;
            const int c16 = id & 7;
            const uint32_t doff = sw_off(r, c16);
            const bool v = r < b_rows;
            const size_t boff = (size_t)(bn + (v ? r : 0)) * ldb + k0 + (c16 << 3);
            cp16(sb + OFF_BH + doff, Bh + boff, v);
            cp16(sb + OFF_BL + doff, Bl + boff, v);
        }
        asm volatile("cp.async.commit_group;" ::: "memory");
    };

    const int span = c_end - c_begin;
    issue_stage(0, c_begin << 6);
    if (span > 1) issue_stage(1, (c_begin + 1) << 6);

    const int lrow = lane & 15;
    const int lhalf = lane >> 4;
    const int a_row0 = warp_m * 32 + lrow;
    const int b_row0 = warp_n * 32 + lrow;

    for (int c = c_begin; c < c_end; c++) {
        if (c + 1 < c_end) asm volatile("cp.async.wait_group 1;" ::: "memory");
        else               asm volatile("cp.async.wait_group 0;" ::: "memory");
        __syncthreads();

        const uint32_t sb = su + (uint32_t)(((c - c_begin) & 1) * STAGE_B);

        uint32_t ah[2][2][4], al[2][2][4];
        {
            const int kc2 = lhalf;
            #pragma unroll
            for (int mt = 0; mt < 2; mt++) {
                const uint32_t ro = sw_off(a_row0 + mt * 16, kc2);
                ldsm_x4(ah[0][mt], sb + ro);
                ldsm_x4(al[0][mt], sb + OFF_AL + ro);
            }
        }

        #pragma unroll
        for (int ks = 0; ks < 4; ks++) {
            const int cur = ks & 1;
            const int kc2 = ks * 2 + lhalf;
            uint32_t bh0[4], bl0[4], bh1[4], bl1[4];
            {
                const uint32_t bo0 = sw_off(b_row0, kc2);
                const uint32_t bo1 = sw_off(b_row0 + 16, kc2);
                ldsm_x4(bh0, sb + OFF_BH + bo0);
                ldsm_x4(bl0, sb + OFF_BL + bo0);
                ldsm_x4(bh1, sb + OFF_BH + bo1);
                ldsm_x4(bl1, sb + OFF_BL + bo1);
            }
            if (ks < 3) {
                const int kn = (ks + 1) * 2 + lhalf;
                #pragma unroll
                for (int mt = 0; mt < 2; mt++) {
                    const uint32_t ro = sw_off(a_row0 + mt * 16, kn);
                    ldsm_x4(ah[cur ^ 1][mt], sb + ro);
                    ldsm_x4(al[cur ^ 1][mt], sb + OFF_AL + ro);
                }
            }
            {
                uint32_t be[2]  = {bh0[0], bh0[2]};
                uint32_t bo2[2] = {bh0[1], bh0[3]};
                uint32_t le[2]  = {bl0[0], bl0[2]};
                uint32_t lo2[2] = {bl0[1], bl0[3]};
                #pragma unroll
                for (int mt = 0; mt < 2; mt++) {
                    mma_bf16(acc[mt][0], ah[cur][mt], be);
                    mma_bf16(acc[mt][0], ah[cur][mt], le);
                    mma_bf16(acc[mt][0], al[cur][mt], be);
                    mma_bf16(acc[mt][1], ah[cur][mt], bo2);
                    mma_bf16(acc[mt][1], ah[cur][mt], lo2);
                    mma_bf16(acc[mt][1], al[cur][mt], bo2);
                }
            }
            {
                uint32_t be[2]  = {bh1[0], bh1[2]};
                uint32_t bo2[2] = {bh1[1], bh1[3]};
                uint32_t le[2]  = {bl1[0], bl1[2]};
                uint32_t lo2[2] = {bl1[1], bl1[3]};
                #pragma unroll
                for (int mt = 0; mt < 2; mt++) {
                    mma_bf16(acc[mt][2], ah[cur][mt], be);
                    mma_bf16(acc[mt][2], ah[cur][mt], le);
                    mma_bf16(acc[mt][2], al[cur][mt], be);
                    mma_bf16(acc[mt][3], ah[cur][mt], bo2);
                    mma_bf16(acc[mt][3], ah[cur][mt], lo2);
                    mma_bf16(acc[mt][3], al[cur][mt], bo2);
                }
            }
        }
        __syncthreads();
        if (c + 2 < c_end)
            issue_stage((c - c_begin) & 1, (c + 2) << 6);
    }

    // epilogue
    #pragma unroll
    for (int mt = 0; mt < 2; mt++) {
        const int r0 = bm + warp_m * 32 + mt * 16 + (lane >> 2);
        #pragma unroll
        for (int nt = 0; nt < 4; nt++) {
            const int col = bn + warp_n * 32 + nt * 8 + ((lane & 3) << 1);
            if (col < N) {
                float v[4];
                #pragma unroll
                for (int q = 0; q < 4; q++) {
                    float val = acc[mt][nt][q];
                    if (EPI == 1) {
                        val += bias[col + (q & 1)];
                        val = fmaxf(val, 0.f) + log1pf(__expf(-fabsf(val)));
                    }
                    if (EPI == 2) {
                        val += bias[col + (q & 1)];
                        val = val / (1.f + __expf(-val));
                    }
                    v[q] = val;
                }
                if (F32S) {
                    *reinterpret_cast<float2*>(&C[(size_t)r0 * ldc + col]) = make_float2(v[0], v[1]);
                    *reinterpret_cast<float2*>(&C[(size_t)(r0 + 8) * ldc + col]) = make_float2(v[2], v[3]);
                }
                if (HLS) {
                    *reinterpret_cast<uint32_t*>(&Chi[(size_t)r0 * ldc + col])       = pack_hi(v[0], v[1]);
                    *reinterpret_cast<uint32_t*>(&Clo[(size_t)r0 * ldc + col])       = pack_lo(v[0], v[1]);
                    *reinterpret_cast<uint32_t*>(&Chi[(size_t)(r0 + 8) * ldc + col]) = pack_hi(v[2], v[3]);
                    *reinterpret_cast<uint32_t*>(&Clo[(size_t)(r0 + 8) * ldc + col]) = pack_lo(v[2], v[3]);
                }
            }
        }
    }
}

// ---------------- split-K reduction for x_dbl ----------------
__global__ __launch_bounds__(256)
void reduce_xdbl_kernel()
{
    int i = blockIdx.x * blockDim.x + threadIdx.x;
    if (i >= MM * NXD) return;
    float s = 0.f;
    #pragma unroll
    for (int z = 0; z < 8; z++) s += g_part[(size_t)z * MM * NXD + i];
    g_xdbl[i] = s;
    __nv_bfloat16 h = __float2bfloat16_rn(s);
    g_xd_hi[i] = h;
    g_xd_lo[i] = __float2bfloat16_rn(s - __bfloat162float(h));
}

// ---------------- causal depthwise conv(4) + SiLU, 4 timesteps/thread ----------------
__global__ __launch_bounds__(256)
void conv_silu_kernel(const float* __restrict__ w, const float* __restrict__ bias)
{
    int idx = blockIdx.x * blockDim.x + threadIdx.x;
    if (idx >= MM * DI / 4) return;
    const int d  = idx & (DI - 1);
    const int g  = idx >> 11;
    const int b  = g >> 9;
    const int l0 = (g & 511) << 2;
    const int m0 = b * LL + l0;

    const float w0 = w[d*4+0], w1 = w[d*4+1], w2 = w[d*4+2], w3 = w[d*4+3];
    const float bs = bias[d];
    const float* base = g_xz + (size_t)m0 * (2 * DI) + d;
    const ptrdiff_t rs = 2 * DI;

    float v[7];
    v[0] = (l0 >= 3) ? base[-3 * rs] : 0.f;
    v[1] = (l0 >= 2) ? base[-2 * rs] : 0.f;
    v[2] = (l0 >= 1) ? base[-1 * rs] : 0.f;
    v[3] = base[0];
    v[4] = base[1 * rs];
    v[5] = base[2 * rs];
    v[6] = base[3 * rs];

    #pragma unroll
    for (int t = 0; t < 4; t++) {
        float acc = bs;
        acc = fmaf(v[t],     w0, acc);
        acc = fmaf(v[t + 1], w1, acc);
        acc = fmaf(v[t + 2], w2, acc);
        acc = fmaf(v[t + 3], w3, acc);
        const float sig = 1.f / (1.f + __expf(-acc));
        const float r = acc * sig;
        const size_t o = (size_t)(m0 + t) * DI + d;
        g_xc[o] = r;
        __nv_bfloat16 h = __float2bfloat16_rn(r);
        g_xc_hi[o] = h;
        g_xc_lo[o] = __float2bfloat16_rn(r - __bfloat162float(h));
    }
}

// ---------------- parallel scan: Pass A ----------------
__global__ __launch_bounds__(256)
void scanA_kernel(const float* __restrict__ A_log)
{
    const int tid  = threadIdx.x;
    const int warp = tid >> 5;
    const int lane = tid & 31;
    const int n = lane & 15;
    const int ch = blockIdx.y;
    const int b  = blockIdx.z;
    const int d  = (blockIdx.x << 4) + (warp << 1) + (lane >> 4);

    const float A = -__expf(A_log[d * DS + n]);
    float h = 0.f, P = 1.f;

    const int t0 = ch * CHL;
    const float* pd = g_delta + (size_t)b * LL * DI + (size_t)t0 * DI + d;
    const float* pu = g_xc    + (size_t)b * LL * DI + (size_t)t0 * DI + d;
    const float* pb = g_xdbl  + (size_t)b * LL * NXD + (size_t)t0 * NXD + DR + n;

    #pragma unroll 4
    for (int t = 0; t < CHL; t++) {
        const float delta = __ldg(pd);
        const float u     = __ldg(pu);
        const float Bn    = __ldg(pb);
        const float e = __expf(delta * A);
        h = fmaf(e, h, delta * u * Bn);
        P *= e;
        pd += DI; pu += DI; pb += NXD;
    }
    const size_t o = ((size_t)(b * NCH + ch) * DI + d) * DS + n;
    gA_P[o] = P;
    gA_h[o] = h;
}

// ---------------- Pass B ----------------
__global__ __launch_bounds__(256)
void scanB_kernel()
{
    int i = blockIdx.x * blockDim.x + threadIdx.x;
    if (i >= BB * DI * DS) return;
    const int b = i / (DI * DS);
    const int r = i % (DI * DS);
    float h = 0.f;
    #pragma unroll
    for (int ch = 0; ch < NCH; ch++) {
        const size_t o = (size_t)(b * NCH + ch) * DI * DS + r;
        gB_in[o] = h;
        h = gA_P[o] * h + gA_h[o];
    }
}

// ---------------- Pass C ----------------
__global__ __launch_bounds__(256)
void scanC_kernel(const float* __restrict__ A_log, const float* __restrict__ Dvec)
{
    const int tid  = threadIdx.x;
    const int warp = tid >> 5;
    const int lane = tid & 31;
    const int n = lane & 15;
    const int ch = blockIdx.y;
    const int b  = blockIdx.z;
    const int d  = (blockIdx.x << 4) + (warp << 1) + (lane >> 4);

    const float A  = -__expf(A_log[d * DS + n]);
    const float Dd = Dvec[d];
    float h = gB_in[((size_t)(b * NCH + ch) * DI + d) * DS + n];

    const int t0 = ch * CHL;
    const float* pd = g_delta + (size_t)b * LL * DI + (size_t)t0 * DI + d;
    const float* pu = g_xc    + (size_t)b * LL * DI + (size_t)t0 * DI + d;
    const float* pz = g_xz    + (size_t)b * LL * (2 * DI) + (size_t)t0 * (2 * DI) + DI + d;
    const float* pb = g_xdbl  + (size_t)b * LL * NXD + (size_t)t0 * NXD + DR + n;
    size_t       oy = (size_t)b * LL * DI + (size_t)t0 * DI + d;

    #pragma unroll 2
    for (int t = 0; t < CHL; t++) {
        const float delta = __ldg(pd);
        const float u     = __ldg(pu);
        const float Bn    = __ldg(pb);
        const float Cn    = __ldg(pb + DS);

        const float e = __expf(delta * A);
        h = fmaf(e, h, delta * u * Bn);

        float p = h * Cn;
        p += __shfl_xor_sync(0xffffffffu, p, 1);
        p += __shfl_xor_sync(0xffffffffu, p, 2);
        p += __shfl_xor_sync(0xffffffffu, p, 4);
        p += __shfl_xor_sync(0xffffffffu, p, 8);

        if (n == 0) {
            const float z = __ldg(pz);
            const float sig = 1.f / (1.f + __expf(-z));
            const float val = (p + Dd * u) * (z * sig);
            __nv_bfloat16 hh = __float2bfloat16_rn(val);
            g_y_hi[oy] = hh;
            g_y_lo[oy] = __float2bfloat16_rn(val - __bfloat162float(hh));
        }
        pd += DI; pu += DI; pz += 2 * DI; pb += NXD; oy += DI;
    }
}

// ---------------- launch ----------------
extern "C" void kernel_launch(void* const* d_in, const int* in_sizes, int n_in,
                              void* d_out, int out_size)
{
    const float* x         = (const float*)d_in[0];
    const float* in_proj_w = (const float*)d_in[1];
    const float* conv_w    = (const float*)d_in[2];
    const float* conv_b    = (const float*)d_in[3];
    const float* x_proj_w  = (const float*)d_in[4];
    const float* dt_proj_w = (const float*)d_in[5];
    const float* dt_proj_b = (const float*)d_in[6];
    const float* A_log     = (const float*)d_in[7];
    const float* Dv        = (const float*)d_in[8];
    const float* ssm_out_w = (const float*)d_in[9];
    const float* final_w   = (const float*)d_in[10];
    const float* final_b   = (const float*)d_in[11];
    float* out = (float*)d_out;

    float *p_xz, *p_delta, *p_part;
    __nv_bfloat16 *x_hi, *x_lo, *w1_hi, *w1_lo, *wx_hi, *wx_lo, *wd_hi, *wd_lo;
    __nv_bfloat16 *wf_hi, *wf_lo, *woT_hi, *woT_lo, *wfo_hi, *wfo_lo;
    __nv_bfloat16 *xc_hi, *xc_lo, *xd_hi, *xd_lo, *y_hi, *y_lo;
    cudaGetSymbolAddress((void**)&p_xz, g_xz);
    cudaGetSymbolAddress((void**)&p_delta, g_delta);
    cudaGetSymbolAddress((void**)&p_part, g_part);
    cudaGetSymbolAddress((void**)&x_hi, g_x_hi);     cudaGetSymbolAddress((void**)&x_lo, g_x_lo);
    cudaGetSymbolAddress((void**)&w1_hi, g_w1_hi);   cudaGetSymbolAddress((void**)&w1_lo, g_w1_lo);
    cudaGetSymbolAddress((void**)&wx_hi, g_wx_hi);   cudaGetSymbolAddress((void**)&wx_lo, g_wx_lo);
    cudaGetSymbolAddress((void**)&wd_hi, g_wd_hi);   cudaGetSymbolAddress((void**)&wd_lo, g_wd_lo);
    cudaGetSymbolAddress((void**)&wf_hi, g_wf_hi);   cudaGetSymbolAddress((void**)&wf_lo, g_wf_lo);
    cudaGetSymbolAddress((void**)&woT_hi, g_woT_hi); cudaGetSymbolAddress((void**)&woT_lo, g_woT_lo);
    cudaGetSymbolAddress((void**)&wfo_hi, g_wfo_hi); cudaGetSymbolAddress((void**)&wfo_lo, g_wfo_lo);
    cudaGetSymbolAddress((void**)&xc_hi, g_xc_hi);   cudaGetSymbolAddress((void**)&xc_lo, g_xc_lo);
    cudaGetSymbolAddress((void**)&xd_hi, g_xd_hi);   cudaGetSymbolAddress((void**)&xd_lo, g_xd_lo);
    cudaGetSymbolAddress((void**)&y_hi, g_y_hi);     cudaGetSymbolAddress((void**)&y_lo, g_y_lo);

    cudaFuncSetAttribute(hmma_gemm<0,true,false>,  cudaFuncAttributeMaxDynamicSharedMemorySize, SMEM_B);
    cudaFuncSetAttribute(hmma_gemm<1,true,false>,  cudaFuncAttributeMaxDynamicSharedMemorySize, SMEM_B);
    cudaFuncSetAttribute(hmma_gemm<0,false,true>,  cudaFuncAttributeMaxDynamicSharedMemorySize, SMEM_B);
    cudaFuncSetAttribute(hmma_gemm<2,true,false>,  cudaFuncAttributeMaxDynamicSharedMemorySize, SMEM_B);

    // side stream for the weight-prep branch (created per call; host-side only)
    cudaStream_t sS;
    cudaStreamCreateWithFlags(&sS, cudaStreamNonBlocking);
    cudaEvent_t eFork, eJoin;
    cudaEventCreateWithFlags(&eFork, cudaEventDisableTiming);
    cudaEventCreateWithFlags(&eJoin, cudaEventDisableTiming);

    // --- main stream: (1) split x, (2) split w1 ---
    split4_kernel<<<(MM*DM/4 + 255)/256, 256>>>((const float4*)x, (uint2*)x_hi, (uint2*)x_lo, MM*DM/4);
    split4_kernel<<<(2*DI*DM/4 + 255)/256, 256>>>((const float4*)in_proj_w, (uint2*)w1_hi, (uint2*)w1_lo, 2*DI*DM/4);

    // fork side branch (independent of main until G3a)
    cudaEventRecord(eFork, 0);
    cudaStreamWaitEvent(sS, eFork, 0);

    // (3, side) split x_proj / dt_proj / final_w
    {
        int n0 = NXD*DI/4, n1 = DI*DR/4, n2 = DM*DM/4;
        split_rest_kernel<<<(n0+n1+n2 + 255)/256, 256, 0, sS>>>(
            (const float4*)x_proj_w,  (uint2*)wx_hi, (uint2*)wx_lo, n0,
            (const float4*)dt_proj_w, (uint2*)wd_hi, (uint2*)wd_lo, n1,
            (const float4*)final_w,   (uint2*)wf_hi, (uint2*)wf_lo, n2);
    }

    // (4, main) G1: in_proj -> g_xz (f32)   [profiled launch]
    hmma_gemm<0,true,false><<<dim3(64,32,1), 256, SMEM_B>>>(
        x_hi, x_lo, DM, w1_hi, w1_lo, DM, p_xz, nullptr, nullptr, 2*DI, 2*DI, DM, nullptr, 0);

    // (5, side) transpose+split ssm_out_w -> woT [DI, DM]
    transpose_split_kernel<<<dim3(DI/32, DM/32), 256, 0, sS>>>(ssm_out_w, woT_hi, woT_lo, DM, DI);

    // (6, side) pre-GEMM: Wfo = final_w @ ssm_out_w -> wfo hi/lo [DM, DI]
    hmma_gemm<0,false,true><<<dim3(DI/64, DM/128, 1), 256, SMEM_B, sS>>>(
        wf_hi, wf_lo, DM, woT_hi, woT_lo, DM, nullptr, wfo_hi, wfo_lo, DI, DI, DM, nullptr, 0);
    cudaEventRecord(eJoin, sS);

    // (7, main) conv + SiLU -> xc f32 + hi/lo
    conv_silu_kernel<<<(MM * DI / 4) / 256, 256>>>(conv_w, conv_b);

    // join side branch before first consumer of wx/wd/wfo
    cudaStreamWaitEvent(0, eJoin, 0);

    // (8) G3a split-K x8: partials = xc @ x_proj_w^T
    hmma_gemm<0,true,false><<<dim3(2,32,8), 256, SMEM_B>>>(
        xc_hi, xc_lo, DI, wx_hi, wx_lo, DI, p_part, nullptr, nullptr, NXD, NXD, DI, nullptr,
        (size_t)MM * NXD);

    // (9) reduce partials -> x_dbl f32 + hi/lo
    reduce_xdbl_kernel<<<(MM*NXD + 255)/256, 256>>>();

    // (10) G3b: delta = softplus(dt @ dt_proj_w^T + b) -> f32
    hmma_gemm<1,true,false><<<dim3(32,32,1), 256, SMEM_B>>>(
        xd_hi, xd_lo, NXD, wd_hi, wd_lo, DR, p_delta, nullptr, nullptr, DI, DI, DR, dt_proj_b, 0);

    // (11-13) parallel scan
    scanA_kernel<<<dim3(128, NCH, BB), 256>>>(A_log);
    scanB_kernel<<<(BB*DI*DS + 255)/256, 256>>>();
    scanC_kernel<<<dim3(128, NCH, BB), 256>>>(A_log, Dv);

    // (14) fused final: out = silu(y @ Wfo^T + final_b)
    hmma_gemm<2,true,false><<<dim3(DM/64, MM/128, 1), 256, SMEM_B>>>(
        y_hi, y_lo, DI, wfo_hi, wfo_lo, DI, out, nullptr, nullptr, DM, DM, DI, final_b, 0);
}